// round 14
// baseline (speedup 1.0000x reference)
#include <cuda_runtime.h>

#define T_STEPS 2000
#define HID 51
#define FEAT 49
#define NTHR 256

typedef unsigned long long ull;

// Hardware tanh (MUFU.TANH): 1 MUFU op.
__device__ __forceinline__ float ftanh(float x) {
    float r;
    asm("tanh.approx.f32 %0, %1;" : "=f"(r) : "f"(x));
    return r;
}
// sigmoid, used only off the hot path (serial LSTM2)
__device__ __forceinline__ float sigm(float x) {
    return fmaf(ftanh(0.5f * x), 0.5f, 0.5f);
}
__device__ __forceinline__ ull pk(float a, float b) {
    ull r;
    asm("mov.b64 %0, {%1, %2};" : "=l"(r) : "f"(a), "f"(b));
    return r;
}
__device__ __forceinline__ ull fma2(ull a, ull b, ull c) {
    ull d;
    asm("fma.rn.f32x2 %0, %1, %2, %3;" : "=l"(d) : "l"(a), "l"(b), "l"(c));
    return d;
}
__device__ __forceinline__ ull add2(ull a, ull b) {
    ull d;
    asm("add.rn.f32x2 %0, %1, %2;" : "=l"(d) : "l"(a), "l"(b));
    return d;
}
__device__ __forceinline__ void upk(ull v, float& a, float& b) {
    asm("mov.b64 {%0, %1}, %2;" : "=f"(a), "=f"(b) : "l"(v));
}

__global__ __launch_bounds__(NTHR, 2)
void lstm_seq_kernel(const float* __restrict__ stim,
                     const float* __restrict__ Wl,   const float* __restrict__ bl,
                     const float* __restrict__ Wih1, const float* __restrict__ Whh1,
                     const float* __restrict__ bih1, const float* __restrict__ bhh1,
                     const float* __restrict__ Wih2, const float* __restrict__ Whh2,
                     const float* __restrict__ bih2, const float* __restrict__ bhh2,
                     const float* __restrict__ Wa,   const float* __restrict__ ba,
                     float* __restrict__ out)
{
    __shared__ float xlin[T_STEPS];                       // 8000 B
    __shared__ __align__(16) float h1_sh[2][52];          // [51] carries xlin[t]
    __shared__ float wl_sh[FEAT];

    const int tid  = threadIdx.x;
    const int lane = tid & 31;
    const int wid  = tid >> 5;
    const int n    = blockIdx.x;

    if (tid < FEAT) wl_sh[tid] = Wl[tid];
    if (tid < 52) { h1_sh[0][tid] = 0.0f; h1_sh[1][tid] = 0.0f; }
    __syncthreads();

    // ---- Phase 0: x_lin = relu(stim . Wl + bl), warp-per-timestep ----
    {
        const float blv = bl[0];
        const float* sb = stim + (size_t)n * T_STEPS * FEAT;
        for (int t = wid; t < T_STEPS; t += 8) {
            const float* p = sb + t * FEAT;
            float s = 0.0f;
            if (lane < FEAT)      s  = p[lane]      * wl_sh[lane];
            if (lane + 32 < FEAT) s += p[lane + 32] * wl_sh[lane + 32];
            #pragma unroll
            for (int off = 16; off; off >>= 1)
                s += __shfl_xor_sync(0xffffffffu, s, off);
            if (lane == 0) xlin[t] = fmaxf(s + blv, 0.0f);
        }
    }

    // ---- Roles ----
    // tid 0..203: gate thread 4j+g owns row g*51+j (g: 0=i,1=f,2=g,3=o).
    //   Sigmoid rows (g!=2) pre-scaled by 0.5: act = 0.5*tanh(pre) + 0.5.
    // warp7 lanes 0..3: LSTM2 input-projection rows; lane0: serial LSTM2;
    //   lane4: x-writer (publishes xlin[t+1] into h buffer slot 51).
    const bool is_gate = (tid < 204);
    const int  j   = tid >> 2;
    const int  g   = tid & 3;

    ull wp[26];
    ull acc_init = 0;
    float sA = 1.0f, sB = 0.0f;      // act = sA*tanh(pre) + sB
    if (is_gate) {
        const int row = g * HID + j;
        const float sc = (g == 2) ? 1.0f : 0.5f;
        if (g != 2) { sA = 0.5f; sB = 0.5f; }
        const float* wr = Whh1 + row * HID;
        #pragma unroll
        for (int q = 0; q < 25; q++)
            wp[q] = pk(sc * wr[2 * q], sc * wr[2 * q + 1]);
        wp[25] = pk(sc * wr[50], sc * Wih1[row]);
        acc_init = pk(sc * (bih1[row] + bhh1[row]), 0.0f);
    } else if (wid == 7 && lane < 4) {
        const float* wr = Wih2 + lane * HID;
        #pragma unroll
        for (int q = 0; q < 25; q++) wp[q] = pk(wr[2 * q], wr[2 * q + 1]);
        wp[25] = pk(wr[50], 0.0f);
        acc_init = pk(bih2[lane] + bhh2[lane], 0.0f);
    }

    float whh2r[4], wav = 0.0f, bav = 0.0f;
    if (wid == 7 && lane < 4) {
        #pragma unroll
        for (int k = 0; k < 4; k++) whh2r[k] = Whh2[k];
        wav = Wa[0];
        bav = ba[0];
    }

    float c1 = 0.0f, h2 = 0.0f, c2 = 0.0f;
    float s0 = 0.0f, s1 = 0.0f, s2 = 0.0f, s3 = 0.0f;
    float* outp = out + (size_t)n * T_STEPS;
    __syncthreads();                       // xlin + weights ready

    if (tid == 0) h1_sh[0][51] = xlin[0];  // seed x for step 0

    // De-phase co-resident CTAs: odd blocks start the recurrence ~300ns late
    // so their compute fills the even blocks' barrier-wait windows (and vice
    // versa). No effect on results; pure scheduling skew.
    if (blockIdx.x & 1) __nanosleep(300);
    __syncthreads();

    const unsigned gmask = (tid < 192) ? 0xffffffffu : 0x0fffu;  // warp6: lanes 0..11
    const int qbase = lane & ~3;           // quad base lane for shfl.idx

    // ---- One recurrence step (t): read hr = h(t-1)|x(t), write hw = h(t). ----
    auto step = [&](int t, const float* hr, float* hw) {
        const ulonglong2* h8 = reinterpret_cast<const ulonglong2*>(hr);

        if (is_gate) {
            if (t < T_STEPS) {
                ull a0 = acc_init, a1 = 0, a2 = 0, a3 = 0;
                #pragma unroll
                for (int q = 0; q < 13; q++) {
                    ulonglong2 v = h8[q];
                    if (q & 1) {
                        a2 = fma2(v.x, wp[2 * q],     a2);
                        a3 = fma2(v.y, wp[2 * q + 1], a3);
                    } else {
                        a0 = fma2(v.x, wp[2 * q],     a0);
                        a1 = fma2(v.y, wp[2 * q + 1], a1);
                    }
                }
                float lo, hi;
                upk(add2(add2(a0, a1), add2(a2, a3)), lo, hi);
                float act = fmaf(ftanh(lo + hi), sA, sB);

                // Branchless quad gather: all 4 lanes get (i,f,g,o) uniformly.
                float gi = __shfl_sync(gmask, act, qbase,     32);
                float gf = __shfl_sync(gmask, act, qbase + 1, 32);
                float gg = __shfl_sync(gmask, act, qbase + 2, 32);
                float go = __shfl_sync(gmask, act, qbase + 3, 32);
                // All lanes update c1 redundantly (identical ops -> identical c1).
                c1 = gf * c1 + gi * gg;
                float hnew = go * ftanh(c1);
                if (g == 0) hw[j] = hnew;               // predicated STS
            }
        } else if (wid == 7) {
            if (lane < 4) {
                // Serial LSTM2 step t-2 (lane 0; p saved from iter t-1)
                if (t >= 2 && lane == 0) {
                    float gi = sigm (s0 + h2 * whh2r[0]);
                    float gf = sigm (s1 + h2 * whh2r[1]);
                    float gg = ftanh(s2 + h2 * whh2r[2]);
                    float go = sigm (s3 + h2 * whh2r[3]);
                    c2 = gf * c2 + gi * gg;
                    h2 = go * ftanh(c2);
                    outp[t - 2] = h2 * wav + bav;
                }
                // p(t-1) = Wih2 . h(t-1) + bias
                if (t >= 1 && t <= T_STEPS) {
                    ull a0 = acc_init, a1 = 0;
                    #pragma unroll
                    for (int q = 0; q < 13; q++) {
                        ulonglong2 v = h8[q];
                        a0 = fma2(v.x, wp[2 * q],     a0);
                        a1 = fma2(v.y, wp[2 * q + 1], a1);
                    }
                    float lo, hi;
                    upk(add2(a0, a1), lo, hi);
                    float p = lo + hi;
                    float q1 = __shfl_xor_sync(0xfu, p, 1);
                    float q2 = __shfl_xor_sync(0xfu, p, 2);
                    float q3 = __shfl_xor_sync(0xfu, p, 3);
                    s0 = p;  s1 = q1;  s2 = q2;  s3 = q3;    // valid on lane 0
                }
            } else if (lane == 4) {
                if (t + 1 < T_STEPS) hw[51] = xlin[t + 1];
            }
        }
        __syncthreads();
    };

    // ---- Recurrence: T+2 steps, 2x unrolled with static ping-pong buffers ----
    for (int tt = 0; tt <= T_STEPS; tt += 2) {
        step(tt,     h1_sh[0], h1_sh[1]);
        step(tt + 1, h1_sh[1], h1_sh[0]);
    }
}

extern "C" void kernel_launch(void* const* d_in, const int* in_sizes, int n_in,
                              void* d_out, int out_size) {
    const float* stim = (const float*)d_in[0];
    const float* Wl   = (const float*)d_in[1];
    const float* bl   = (const float*)d_in[2];
    const float* Wih1 = (const float*)d_in[3];
    const float* Whh1 = (const float*)d_in[4];
    const float* bih1 = (const float*)d_in[5];
    const float* bhh1 = (const float*)d_in[6];
    const float* Wih2 = (const float*)d_in[7];
    const float* Whh2 = (const float*)d_in[8];
    const float* bih2 = (const float*)d_in[9];
    const float* bhh2 = (const float*)d_in[10];
    const float* Wa   = (const float*)d_in[11];
    const float* ba   = (const float*)d_in[12];

    const int N = out_size / T_STEPS;   // 256
    lstm_seq_kernel<<<N, NTHR>>>(stim, Wl, bl, Wih1, Whh1, bih1, bhh1,
                                 Wih2, Whh2, bih2, bhh2, Wa, ba,
                                 (float*)d_out);
}

// round 17
// speedup vs baseline: 1.1945x; 1.1945x over previous
#include <cuda_runtime.h>
#include <cuda_fp16.h>

#define T_STEPS 2000
#define HID 51
#define FEAT 49
#define NTHR 256

// Hardware tanh (MUFU.TANH): 1 MUFU op.
__device__ __forceinline__ float ftanh(float x) {
    float r;
    asm("tanh.approx.f32 %0, %1;" : "=f"(r) : "f"(x));
    return r;
}
// sigmoid, used only off the hot path (serial LSTM2)
__device__ __forceinline__ float sigm(float x) {
    return fmaf(ftanh(0.5f * x), 0.5f, 0.5f);
}

__global__ __launch_bounds__(NTHR, 2)
void lstm_seq_kernel(const float* __restrict__ stim,
                     const float* __restrict__ Wl,   const float* __restrict__ bl,
                     const float* __restrict__ Wih1, const float* __restrict__ Whh1,
                     const float* __restrict__ bih1, const float* __restrict__ bhh1,
                     const float* __restrict__ Wih2, const float* __restrict__ Whh2,
                     const float* __restrict__ bih2, const float* __restrict__ bhh2,
                     const float* __restrict__ Wa,   const float* __restrict__ ba,
                     float* __restrict__ out)
{
    __shared__ float xlin[T_STEPS];                          // 8000 B
    __shared__ __align__(16) __half h1_sh[2][56];            // fp16 h | [51]=x | 52..55=0
    __shared__ float wl_sh[FEAT];

    const int tid  = threadIdx.x;
    const int lane = tid & 31;
    const int wid  = tid >> 5;
    const int n    = blockIdx.x;

    if (tid < FEAT) wl_sh[tid] = Wl[tid];
    if (tid < 56) { h1_sh[0][tid] = __float2half_rn(0.0f); h1_sh[1][tid] = __float2half_rn(0.0f); }
    __syncthreads();

    // ---- Phase 0: x_lin = relu(stim . Wl + bl), warp-per-timestep ----
    {
        const float blv = bl[0];
        const float* sb = stim + (size_t)n * T_STEPS * FEAT;
        for (int t = wid; t < T_STEPS; t += 8) {
            const float* p = sb + t * FEAT;
            float s = 0.0f;
            if (lane < FEAT)      s  = p[lane]      * wl_sh[lane];
            if (lane + 32 < FEAT) s += p[lane + 32] * wl_sh[lane + 32];
            #pragma unroll
            for (int off = 16; off; off >>= 1)
                s += __shfl_xor_sync(0xffffffffu, s, off);
            if (lane == 0) xlin[t] = fmaxf(s + blv, 0.0f);
        }
    }

    // ---- Roles ----
    // tid 0..203: gate thread 4j+g owns row g*51+j (g: 0=i,1=f,2=g,3=o).
    //   Sigmoid rows (g!=2) pre-scaled by 0.5: act = 0.5*tanh(pre) + 0.5.
    // warp7 lanes 0..3: LSTM2 input-projection rows; lane0: serial LSTM2;
    //   lane4: x-writer (publishes xlin[t+1] into h buffer slot 51).
    const bool is_gate = (tid < 204);
    const int  j   = tid >> 2;
    const int  g   = tid & 3;

    // 26 half2 weight registers: halves 0..49 = w[0..49], (w50, wih) in unit 25.
    __half2 wh[26];
    float bias = 0.0f;
    float sA = 1.0f, sB = 0.0f;      // act = sA*tanh(pre) + sB
    if (is_gate) {
        const int row = g * HID + j;
        const float sc = (g == 2) ? 1.0f : 0.5f;
        if (g != 2) { sA = 0.5f; sB = 0.5f; }
        const float* wr = Whh1 + row * HID;
        #pragma unroll
        for (int q = 0; q < 25; q++)
            wh[q] = __floats2half2_rn(sc * wr[2 * q], sc * wr[2 * q + 1]);
        wh[25] = __floats2half2_rn(sc * wr[50], sc * Wih1[row]);
        bias = sc * (bih1[row] + bhh1[row]);
    } else if (wid == 7 && lane < 4) {
        const float* wr = Wih2 + lane * HID;
        #pragma unroll
        for (int q = 0; q < 25; q++)
            wh[q] = __floats2half2_rn(wr[2 * q], wr[2 * q + 1]);
        wh[25] = __floats2half2_rn(wr[50], 0.0f);
        bias = bih2[lane] + bhh2[lane];
    }

    float whh2r[4], wav = 0.0f, bav = 0.0f;
    if (wid == 7 && lane < 4) {
        #pragma unroll
        for (int k = 0; k < 4; k++) whh2r[k] = Whh2[k];
        wav = Wa[0];
        bav = ba[0];
    }

    float c1 = 0.0f, h2 = 0.0f, c2 = 0.0f;
    float s0 = 0.0f, s1 = 0.0f, s2 = 0.0f, s3 = 0.0f;
    float* outp = out + (size_t)n * T_STEPS;
    __syncthreads();                       // xlin + weights ready

    if (tid == 0) h1_sh[0][51] = __float2half_rn(xlin[0]);   // seed x for step 0
    __syncthreads();

    const unsigned gmask = (tid < 192) ? 0xffffffffu : 0x0fffu;  // warp6: lanes 0..11
    const int qbase = lane & ~3;           // quad base lane for shfl.idx

    // GEMV over the fp16 h buffer: 7 x LDS.128 (uint4 = 4 half2), 26 HFMA2.
    // Returns fp32 dot; caller adds bias.
    auto dot26 = [&](const uint4* h16) -> float {
        __half2 a0 = __floats2half2_rn(0.f, 0.f), a1 = a0, a2 = a0, a3 = a0;
        uint4 v0 = h16[0], v1 = h16[1], v2 = h16[2], v3 = h16[3];
        uint4 v4 = h16[4], v5 = h16[5], v6 = h16[6];
        const __half2* p0 = reinterpret_cast<const __half2*>(&v0);
        const __half2* p1 = reinterpret_cast<const __half2*>(&v1);
        const __half2* p2 = reinterpret_cast<const __half2*>(&v2);
        const __half2* p3 = reinterpret_cast<const __half2*>(&v3);
        const __half2* p4 = reinterpret_cast<const __half2*>(&v4);
        const __half2* p5 = reinterpret_cast<const __half2*>(&v5);
        const __half2* p6 = reinterpret_cast<const __half2*>(&v6);
        #pragma unroll
        for (int k = 0; k < 4; k++) {
            a0 = __hfma2(p0[k], wh[k],      a0);
            a1 = __hfma2(p1[k], wh[4 + k],  a1);
            a2 = __hfma2(p2[k], wh[8 + k],  a2);
            a3 = __hfma2(p3[k], wh[12 + k], a3);
        }
        #pragma unroll
        for (int k = 0; k < 4; k++) {
            a0 = __hfma2(p4[k], wh[16 + k], a0);
            a1 = __hfma2(p5[k], wh[20 + k], a1);
        }
        a2 = __hfma2(p6[0], wh[24], a2);
        a3 = __hfma2(p6[1], wh[25], a3);
        __half2 s = __hadd2(__hadd2(a0, a1), __hadd2(a2, a3));
        float2 f = __half22float2(s);
        return f.x + f.y;
    };

    // ---- Recurrence: T+2 iterations, ONE barrier per iteration ----
    for (int t = 0; t <= T_STEPS + 1; t++) {
        const uint4* h16 = reinterpret_cast<const uint4*>(h1_sh[t & 1]);
        __half* hw = h1_sh[(t + 1) & 1];

        if (is_gate) {
            if (t < T_STEPS) {
                float pre = dot26(h16) + bias;
                float act = fmaf(ftanh(pre), sA, sB);

                // Branchless quad gather: all 4 lanes get (i,f,g,o) uniformly.
                float gi = __shfl_sync(gmask, act, qbase,     32);
                float gf = __shfl_sync(gmask, act, qbase + 1, 32);
                float gg = __shfl_sync(gmask, act, qbase + 2, 32);
                float go = __shfl_sync(gmask, act, qbase + 3, 32);
                // All lanes update c1 redundantly (identical ops -> identical c1).
                c1 = gf * c1 + gi * gg;
                float hnew = go * ftanh(c1);
                if (g == 0) hw[j] = __float2half_rn(hnew);   // predicated 16-bit STS
            }
        } else if (wid == 7) {
            if (lane < 4) {
                // Serial LSTM2 step t-2 (lane 0; p saved from iter t-1)
                if (t >= 2 && lane == 0) {
                    float gi = sigm (s0 + h2 * whh2r[0]);
                    float gf = sigm (s1 + h2 * whh2r[1]);
                    float gg = ftanh(s2 + h2 * whh2r[2]);
                    float go = sigm (s3 + h2 * whh2r[3]);
                    c2 = gf * c2 + gi * gg;
                    h2 = go * ftanh(c2);
                    outp[t - 2] = h2 * wav + bav;
                }
                // p(t-1) = Wih2 . h(t-1) + bias
                if (t >= 1 && t <= T_STEPS) {
                    float p = dot26(h16) + bias;
                    float q1 = __shfl_xor_sync(0xfu, p, 1);
                    float q2 = __shfl_xor_sync(0xfu, p, 2);
                    float q3 = __shfl_xor_sync(0xfu, p, 3);
                    s0 = p;  s1 = q1;  s2 = q2;  s3 = q3;    // valid on lane 0
                }
            } else if (lane == 4) {
                if (t + 1 < T_STEPS) hw[51] = __float2half_rn(xlin[t + 1]);
            }
        }
        __syncthreads();
    }
}

extern "C" void kernel_launch(void* const* d_in, const int* in_sizes, int n_in,
                              void* d_out, int out_size) {
    const float* stim = (const float*)d_in[0];
    const float* Wl   = (const float*)d_in[1];
    const float* bl   = (const float*)d_in[2];
    const float* Wih1 = (const float*)d_in[3];
    const float* Whh1 = (const float*)d_in[4];
    const float* bih1 = (const float*)d_in[5];
    const float* bhh1 = (const float*)d_in[6];
    const float* Wih2 = (const float*)d_in[7];
    const float* Whh2 = (const float*)d_in[8];
    const float* bih2 = (const float*)d_in[9];
    const float* bhh2 = (const float*)d_in[10];
    const float* Wa   = (const float*)d_in[11];
    const float* ba   = (const float*)d_in[12];

    const int N = out_size / T_STEPS;   // 256
    lstm_seq_kernel<<<N, NTHR>>>(stim, Wl, bl, Wih1, Whh1, bih1, bhh1,
                                 Wih2, Whh2, bih2, bhh2, Wa, ba,
                                 (float*)d_out);
}